// round 16
// baseline (speedup 1.0000x reference)
#include <cuda_runtime.h>
#include <cstdint>

// z: (64,13,128,128) fp32
#define BB 64
#define CC 13
#define HWSZ 16384                       // 128*128
#define NPIX (BB*HWSZ)                   // 1,048,576
#define NTOT (CC*NPIX)                   // 13,631,488

#define THREADS 256
#define PIX_PER_BLK 512                  // 256 threads * 2 pixels
#define F_BLOCKS (NPIX / PIX_PER_BLK)    // 2048
#define BLKS_PER_IMG (HWSZ / PIX_PER_BLK) // 32

// Deterministic scratch (fully overwritten every launch; no runtime allocs).
__device__ float2 g_ce[F_BLOCKS];                 // per-block {commit, ent}
__device__ float g_chsum[CC * F_BLOCKS];          // channel-major p0 partials

__device__ __forceinline__ float warp_sum(float v) {
    #pragma unroll
    for (int o = 16; o; o >>= 1) v += __shfl_xor_sync(0xffffffffu, v, o);
    return v;
}

__device__ __forceinline__ void proc(float zv, float& q, float& commit,
                                     float& ent, float& ca, int& idx) {
    bool pos = zv > 0.0f;
    q = pos ? 1.0f : -1.0f;
    float az = fabsf(zv);
    float d = 1.0f - az;
    commit = fmaf(d, d, commit);
    float a = 4.0f * az;                  // |l0 - l1|
    float e = __expf(-a);                 // in (0,1]
    float r = __fdividef(1.0f, 1.0f + e); // sigmoid(a)
    float ps = e * r;                     // 1 - sigmoid(a)
    ent += fmaf(a, ps, __logf(1.0f + e)); // H(p)
    ca += pos ? r : ps;                   // p0 = sigmoid(4z)
    idx = (idx << 1) | (pos ? 1 : 0);     // MSB = channel 0
}

// ---- Fused: quantize + partials + in-register bitpack, MLP=13 upfront loads ----
__global__ void __launch_bounds__(THREADS)
lfq_fused(const float* __restrict__ z, float* __restrict__ out) {
    int tid = threadIdx.x;
    int blk = blockIdx.x;
    int b    = blk >> 5;                  // image
    int part = blk & (BLKS_PER_IMG - 1);
    int off  = part * PIX_PER_BLK + tid * 2;
    size_t base = (size_t)b * (CC * HWSZ) + off;

    // all 13 channels loaded upfront: 13 independent LDG.64, MLP = 13
    float2 v[CC];
    #pragma unroll
    for (int c = 0; c < CC; c++)
        v[c] = *reinterpret_cast<const float2*>(z + base + (size_t)c * HWSZ);

    float commit = 0.0f, ent = 0.0f;
    float ch[CC];
    int i0 = 0, i1 = 0;

    #pragma unroll
    for (int c = 0; c < CC; c++) {
        float2 qv;
        float ca = 0.0f;
        proc(v[c].x, qv.x, commit, ent, ca, i0);
        proc(v[c].y, qv.y, commit, ent, ca, i1);
        *reinterpret_cast<float2*>(out + base + (size_t)c * HWSZ) = qv;
        ch[c] = ca;
    }

    // indices straight from registers (8B-aligned region -> float2 store)
    float* idx_out = out + NTOT + 2;
    int pix = b * HWSZ + off;
    *reinterpret_cast<float2*>(idx_out + pix) = make_float2((float)i0, (float)i1);

    // ---- reductions: 15 interleaved shuffle chains AFTER the hot loop ----
    commit = warp_sum(commit);
    ent    = warp_sum(ent);
    #pragma unroll
    for (int c = 0; c < CC; c++) ch[c] = warp_sum(ch[c]);

    __shared__ float sch[CC][8];
    __shared__ float sw[2][8];
    int w = tid >> 5, lane = tid & 31;
    if (lane == 0) {
        sw[0][w] = commit;
        sw[1][w] = ent;
        #pragma unroll
        for (int c = 0; c < CC; c++) sch[c][w] = ch[c];
    }
    __syncthreads();
    if (tid < CC) {                        // thread c sums channel c across 8 warps
        float s = 0.0f;
        #pragma unroll
        for (int i = 0; i < 8; i++) s += sch[tid][i];
        g_chsum[tid * F_BLOCKS + blk] = s; // channel-major
    } else if (tid == 16) {
        float c0 = 0.0f, e0 = 0.0f;
        #pragma unroll
        for (int i = 0; i < 8; i++) { c0 += sw[0][i]; e0 += sw[1][i]; }
        g_ce[blk] = make_float2(c0, e0);
    }
}

// ---- Finalize: one block, coalesced reads, parallel fp32 logs ----
__global__ void __launch_bounds__(512)
lfq_finalize(float* __restrict__ out) {
    int tid = threadIdx.x;
    int w = tid >> 5, lane = tid & 31;
    __shared__ float sce[2][16];
    __shared__ float sch[CC];
    __shared__ float sment;

    // commit/ent: 2048 contiguous float2, 4 coalesced iterations
    float commit = 0.0f, ent = 0.0f;
    #pragma unroll
    for (int r = tid; r < F_BLOCKS; r += 512) {
        float2 u = g_ce[r];
        commit += u.x;
        ent    += u.y;
    }
    commit = warp_sum(commit);
    ent    = warp_sum(ent);
    if (lane == 0) { sce[0][w] = commit; sce[1][w] = ent; }

    // channel sums: warp w (<13) owns channel w: 2048 contiguous floats as float4
    if (w < CC) {
        const float4* cp = reinterpret_cast<const float4*>(&g_chsum[w * F_BLOCKS]);
        float chs = 0.0f;
        #pragma unroll
        for (int k = 0; k < F_BLOCKS / 4 / 32; k++) {   // 16 float4 per lane
            float4 u = cp[lane + 32 * k];
            chs += (u.x + u.y) + (u.z + u.w);
        }
        chs = warp_sum(chs);
        if (lane == 0) sch[w] = chs;
    }
    __syncthreads();

    // mean-entropy: 13 lanes of warp 0, parallel fp32 logs
    if (tid < 32) {
        float me = 0.0f;
        if (tid < CC) {
            float mp = sch[tid] * (1.0f / (float)NPIX);
            mp = fminf(fmaxf(mp, 1e-12f), 1.0f - 1e-7f);
            float mq = 1.0f - mp;
            me = -(mp * __logf(mp) + mq * __logf(mq));
        }
        me = warp_sum(me);
        if (tid == 0) sment = me * (1.0f / (float)CC);
    }
    __syncthreads();

    if (tid == 0) {
        float c0 = 0.0f, e0 = 0.0f;
        #pragma unroll
        for (int i = 0; i < 16; i++) { c0 += sce[0][i]; e0 += sce[1][i]; }
        out[NTOT]     = c0 * (float)(1.25 * 0.1 / (double)NTOT);
        out[NTOT + 1] = (e0 * (float)(1.0 / (double)NTOT) - sment) * 0.1f;
    }
}

extern "C" void kernel_launch(void* const* d_in, const int* in_sizes, int n_in,
                              void* d_out, int out_size) {
    const float* z = (const float*)d_in[0];
    float* out = (float*)d_out;
    lfq_fused<<<F_BLOCKS, THREADS>>>(z, out);
    lfq_finalize<<<1, 512>>>(out);
}

// round 17
// speedup vs baseline: 1.2379x; 1.2379x over previous
#include <cuda_runtime.h>
#include <cstdint>

// z: (64,13,128,128) fp32
#define BB 64
#define CC 13
#define HWSZ 16384                       // 128*128
#define NPIX (BB*HWSZ)                   // 1,048,576
#define NTOT (CC*NPIX)                   // 13,631,488
#define NPLANES (BB*CC)                  // 832
#define THREADS 256

#define A_BLOCKS (NPLANES*4)             // 3328: one quarter of one (b,c) plane each
#define SLOTS 256                        // per-channel partial slots (64 imgs * 4 quarters)

#define PACK_BLOCKS 512
#define RED_BLOCKS 16
#define ROWS_PER_RED (A_BLOCKS / RED_BLOCKS)   // 208 = 13*16

// Deterministic scratch (fully overwritten / self-resetting every launch).
__device__ float2 g_ce[A_BLOCKS];                 // per-block {commit, ent}
__device__ float g_chsum[CC * SLOTS];             // channel-major p0 partials
__device__ unsigned char g_signs[NTOT/4];         // 4 sign bits/byte (low nibble)
__device__ float g_l2[RED_BLOCKS * 16];           // level-2 partials: [commit,ent,ch0..12,pad]
__device__ unsigned int g_fcnt;                   // wraps at 16 increments

__device__ __forceinline__ float warp_sum(float v) {
    #pragma unroll
    for (int o = 16; o; o >>= 1) v += __shfl_xor_sync(0xffffffffu, v, o);
    return v;
}

__device__ __forceinline__ void proc(float zv, float& q, float& commit,
                                     float& ent, float& ch, unsigned& byte, int k) {
    bool pos = zv > 0.0f;
    q = pos ? 1.0f : -1.0f;
    float az = fabsf(zv);
    float d = 1.0f - az;
    commit = fmaf(d, d, commit);
    float a = 4.0f * az;                  // |l0 - l1|
    float e = __expf(-a);                 // in (0,1]
    float r = __fdividef(1.0f, 1.0f + e); // sigmoid(a)
    float ps = e * r;                     // 1 - sigmoid(a)
    ent += fmaf(a, ps, __logf(1.0f + e)); // H(p)
    ch += pos ? r : ps;                   // p0 = sigmoid(4z)
    byte |= (pos ? 1u : 0u) << k;
}

// ---------------- Kernel A: quantize + partial sums + sign bytes ----------------
__global__ void __launch_bounds__(THREADS)
lfq_planes(const float* __restrict__ z, float* __restrict__ out) {
    int tid = threadIdx.x;
    int blk = blockIdx.x;
    int p       = blk >> 2;               // plane id = b*13 + c
    int quarter = blk & 3;
    size_t base = (size_t)p * HWSZ + quarter * 4096 + tid * 4;

    float4 v[4];
    #pragma unroll
    for (int i = 0; i < 4; i++)
        v[i] = *reinterpret_cast<const float4*>(z + base + i * 1024);

    float commit = 0.0f, ent = 0.0f, ch = 0.0f;
    int sbase = p * 4096 + quarter * 1024 + tid;
    #pragma unroll
    for (int i = 0; i < 4; i++) {
        float4 q;
        unsigned byte = 0;
        proc(v[i].x, q.x, commit, ent, ch, byte, 0);
        proc(v[i].y, q.y, commit, ent, ch, byte, 1);
        proc(v[i].z, q.z, commit, ent, ch, byte, 2);
        proc(v[i].w, q.w, commit, ent, ch, byte, 3);
        *reinterpret_cast<float4*>(out + base + i * 1024) = q;
        g_signs[sbase + i * 256] = (unsigned char)byte;   // byte s covers pixels 4s..4s+3
    }

    commit = warp_sum(commit);
    ent    = warp_sum(ent);
    ch     = warp_sum(ch);
    __shared__ float sw[3][8];
    int w = tid >> 5;
    if ((tid & 31) == 0) { sw[0][w] = commit; sw[1][w] = ent; sw[2][w] = ch; }
    __syncthreads();
    if (tid == 0) {
        float c0 = 0, e0 = 0, h0 = 0;
        #pragma unroll
        for (int i = 0; i < 8; i++) { c0 += sw[0][i]; e0 += sw[1][i]; h0 += sw[2][i]; }
        g_ce[blk] = make_float2(c0, e0);
        int b = p / CC, c = p - b * CC;
        g_chsum[c * SLOTS + b * 4 + quarter] = h0;    // channel-major
    }
}

// ---- Kernel B: 512 pack blocks + 16 hierarchical reducer blocks ----------------
__global__ void __launch_bounds__(512)
lfq_pack_reduce(float* __restrict__ out) {
    int tid = threadIdx.x;

    if (blockIdx.x < PACK_BLOCKS) {
        // ---------------- pack: 4 px/thread, L2-hot byte gather ----------------
        float* idx_out = out + NTOT + 2;        // 8B-aligned region -> float2 stores
        int g = blockIdx.x * 512 + tid;         // pixel-group id, [0, NPIX/4)
        int b = g >> 12;                        // 4096 groups per batch image
        int local = g & 4095;
        int i0 = 0, i1 = 0, i2 = 0, i3 = 0;
        #pragma unroll
        for (int c = 0; c < CC; c++) {          // MSB = channel 0
            unsigned byte = g_signs[(b * CC + c) * 4096 + local];
            i0 = (i0 << 1) | (byte & 1);
            i1 = (i1 << 1) | ((byte >> 1) & 1);
            i2 = (i2 << 1) | ((byte >> 2) & 1);
            i3 = (i3 << 1) | ((byte >> 3) & 1);
        }
        int pix = g * 4;
        *reinterpret_cast<float2*>(idx_out + pix)     = make_float2((float)i0, (float)i1);
        *reinterpret_cast<float2*>(idx_out + pix + 2) = make_float2((float)i2, (float)i3);
        return;
    }

    // ---------------- reducer block rb in [0,16) ----------------
    int rb = blockIdx.x - PACK_BLOCKS;
    int w = tid >> 5, lane = tid & 31;

    // commit/ent: rows [rb*208, rb*208+208), one float2 per thread (tid<208)
    float c0 = 0.0f, e0 = 0.0f;
    if (tid < ROWS_PER_RED) {
        float2 u = g_ce[rb * ROWS_PER_RED + tid];
        c0 = u.x; e0 = u.y;
    }
    c0 = warp_sum(c0);
    e0 = warp_sum(e0);
    __shared__ float swc[16], swe[16], smch[CC], sce[2];
    if (lane == 0) { swc[w] = c0; swe[w] = e0; }

    // channel partials: tid<208: c = tid/16, slot = rb*16 + tid%16
    float chv = (tid < ROWS_PER_RED)
        ? g_chsum[(tid >> 4) * SLOTS + rb * 16 + (tid & 15)] : 0.0f;
    #pragma unroll
    for (int o = 1; o < 16; o <<= 1) chv += __shfl_xor_sync(0xffffffffu, chv, o);
    if (tid < ROWS_PER_RED && (tid & 15) == 0) smch[tid >> 4] = chv;
    __syncthreads();

    if (tid == 0) {
        float a = 0.0f, b2 = 0.0f;
        #pragma unroll
        for (int i = 0; i < 16; i++) { a += swc[i]; b2 += swe[i]; }
        sce[0] = a; sce[1] = b2;
    }
    __syncthreads();
    if (tid < 16) {
        float v = (tid < 2) ? sce[tid] : (tid < 15 ? smch[tid - 2] : 0.0f);
        g_l2[rb * 16 + tid] = v;
    }

    // ---------------- ticket: last reducer folds 16 rows + scalars ----------------
    __shared__ unsigned s_old;
    __threadfence();                       // release g_l2 row
    __syncthreads();
    if (tid == 0) s_old = atomicInc(&g_fcnt, RED_BLOCKS - 1);  // wraps to 0 after 16
    __syncthreads();
    if (s_old != RED_BLOCKS - 1) return;
    __threadfence();                       // acquire all g_l2 rows

    __shared__ float S[16];
    __shared__ float sment;
    if (tid < 16) {
        float s = 0.0f;
        #pragma unroll
        for (int r = 0; r < RED_BLOCKS; r++) s += g_l2[r * 16 + tid];
        S[tid] = s;                        // S[0]=commit, S[1]=ent, S[2+c]=ch_c
    }
    __syncthreads();

    if (tid < 32) {
        float me = 0.0f;
        if (tid < CC) {
            float mp = S[2 + tid] * (1.0f / (float)NPIX);
            mp = fminf(fmaxf(mp, 1e-12f), 1.0f - 1e-7f);
            float mq = 1.0f - mp;
            me = -(mp * __logf(mp) + mq * __logf(mq));
        }
        me = warp_sum(me);
        if (tid == 0) sment = me * (1.0f / (float)CC);
    }
    __syncthreads();

    if (tid == 0) {
        out[NTOT]     = S[0] * (float)(1.25 * 0.1 / (double)NTOT);
        out[NTOT + 1] = (S[1] * (float)(1.0 / (double)NTOT) - sment) * 0.1f;
    }
}

extern "C" void kernel_launch(void* const* d_in, const int* in_sizes, int n_in,
                              void* d_out, int out_size) {
    const float* z = (const float*)d_in[0];
    float* out = (float*)d_out;
    lfq_planes<<<A_BLOCKS, THREADS>>>(z, out);
    lfq_pack_reduce<<<PACK_BLOCKS + RED_BLOCKS, 512>>>(out);
}